// round 14
// baseline (speedup 1.0000x reference)
#include <cuda_runtime.h>
#include <cuda_bf16.h>
#include <cstdint>
#include <math.h>

#define BN 512
#define CC 3
#define NP 49
#define NT 76
#define DD 768
#define EPSI 0.1f
#define THRESH 0.01f
#define MAX_ITER 100

#define NBLK 128          // sinkhorn persistent blocks
#define STPB 512          // sinkhorn threads per block (16 warps)
#define SKP (49*77)       // padded K tile stride (3773 floats)
#define KSPLIT 6
#define GEMM_BLKS 384     // 8 x 8 x 6 split-K tiles

// ------------------------- device scratch (no allocs allowed) ----------------
__device__ float g_K[(size_t)CC*BN*NP*NT];        // exp kernel per (c,b)
__device__ float g_Gp[(size_t)KSPLIT*BN*BN];      // split-K partials of logits GEMM
__device__ float g_LT[(size_t)BN*BN];             // logits TRANSPOSED [col][row]
__device__ float g_lse_row[BN];
__device__ float g_lse_col[BN];
__device__ float4 g_err4[NBLK];
__device__ float g_ot_part[NBLK];
__device__ unsigned g_count;
__device__ unsigned g_gen;
__device__ unsigned g_mask;
__device__ unsigned g_fin1;
__device__ unsigned g_fin2;

__device__ __forceinline__ uint32_t pack_bf16(float x, float y) {
    __nv_bfloat162 h = __floats2bfloat162_rn(x, y);  // .x = low 16 bits
    return *reinterpret_cast<uint32_t*>(&h);
}
__device__ __forceinline__ uint32_t f2tf(float x) {
    uint32_t r;
    asm("cvt.rna.tf32.f32 %0, %1;" : "=r"(r) : "f"(x));
    return r;
}
__device__ __forceinline__ unsigned ld_acq(const unsigned* p) {
    unsigned v;
    asm volatile("ld.acquire.gpu.u32 %0, [%1];" : "=r"(v) : "l"(p));
    return v;
}
__device__ __forceinline__ void ldsm_x4(uint32_t& d0, uint32_t& d1,
                                        uint32_t& d2, uint32_t& d3, uint32_t addr) {
    asm volatile("ldmatrix.sync.aligned.m8n8.x4.shared.b16 {%0,%1,%2,%3}, [%4];"
                 : "=r"(d0), "=r"(d1), "=r"(d2), "=r"(d3) : "r"(addr));
}
__device__ __forceinline__ void ldsm_x2(uint32_t& d0, uint32_t& d1, uint32_t addr) {
    asm volatile("ldmatrix.sync.aligned.m8n8.x2.shared.b16 {%0,%1}, [%2];"
                 : "=r"(d0), "=r"(d1) : "r"(addr));
}

// ---------------- fused kernel: logits GEMM (blocks 0..383) ------------------
//                + simK        (blocks 384..1919)
__device__ void gemm_part(uint32_t* smem, int g,
                          const float* __restrict__ img,
                          const float* __restrict__ txt) {
    uint32_t* As = smem;            // 4608 words (2 bufs of 64*36)
    uint32_t* Bs = smem + 4608;     // 4608 words
    const int bz = g >> 6;
    const int by = (g & 63) >> 3;
    const int bx = g & 7;
    const int t = threadIdx.x;
    const int lane = t & 31, w = t >> 5;
    const int gid = lane >> 2, tig = lane & 3;
    const int wm = w >> 1, wn = w & 1;
    const int rowA = by * 64, rowB = bx * 64;
    const float4* A4 = reinterpret_cast<const float4*>(img);
    const float4* B4 = reinterpret_cast<const float4*>(txt);
    const int lr = t >> 2;
    const int lj = t & 3;
    const int kbase = bz * 96;

    float acc[4][4];
    #pragma unroll
    for (int f = 0; f < 4; f++) {
        acc[f][0] = 0.f; acc[f][1] = 0.f; acc[f][2] = 0.f; acc[f][3] = 0.f;
    }

    float4 va0, va1, vb0, vb1;
    auto gload = [&](int kc) {
        const size_t offA = (size_t)(rowA + lr)*576 + kbase + kc*8 + lj*2;
        const size_t offB = (size_t)(rowB + lr)*576 + kbase + kc*8 + lj*2;
        va0 = A4[offA]; va1 = A4[offA + 1];
        vb0 = B4[offB]; vb1 = B4[offB + 1];
    };
    auto sstore = [&](int buf) {
        uint4* pa = reinterpret_cast<uint4*>(&As[buf*2304 + lr*36 + lj*8]);
        uint4* pb = reinterpret_cast<uint4*>(&Bs[buf*2304 + lr*36 + lj*8]);
        pa[0] = make_uint4(f2tf(va0.x), f2tf(va0.y), f2tf(va0.z), f2tf(va0.w));
        pa[1] = make_uint4(f2tf(va1.x), f2tf(va1.y), f2tf(va1.z), f2tf(va1.w));
        pb[0] = make_uint4(f2tf(vb0.x), f2tf(vb0.y), f2tf(vb0.z), f2tf(vb0.w));
        pb[1] = make_uint4(f2tf(vb1.x), f2tf(vb1.y), f2tf(vb1.z), f2tf(vb1.w));
    };

    gload(0);
    sstore(0);
    __syncthreads();

    for (int kc = 0; kc < 12; kc++) {
        const int buf = kc & 1;
        const uint32_t* Ab = &As[buf*2304];
        const uint32_t* Bb = &Bs[buf*2304];
        if (kc < 11) gload(kc + 1);
        #pragma unroll
        for (int ks = 0; ks < 4; ks++) {
            const int kw = ks * 8;
            uint32_t a0 = Ab[(wm*16 + gid)*36 + kw + tig];
            uint32_t a1 = Ab[(wm*16 + gid + 8)*36 + kw + tig];
            uint32_t a2 = Ab[(wm*16 + gid)*36 + kw + 4 + tig];
            uint32_t a3 = Ab[(wm*16 + gid + 8)*36 + kw + 4 + tig];
            #pragma unroll
            for (int f = 0; f < 4; f++) {
                int col = wn*32 + f*8 + gid;
                uint32_t b0 = Bb[col*36 + kw + tig];
                uint32_t b1 = Bb[col*36 + kw + 4 + tig];
                asm volatile(
                    "mma.sync.aligned.m16n8k8.row.col.f32.tf32.tf32.f32 "
                    "{%0,%1,%2,%3}, {%4,%5,%6,%7}, {%8,%9}, {%0,%1,%2,%3};"
                    : "+f"(acc[f][0]), "+f"(acc[f][1]), "+f"(acc[f][2]), "+f"(acc[f][3])
                    : "r"(a0), "r"(a1), "r"(a2), "r"(a3), "r"(b0), "r"(b1));
            }
        }
        if (kc < 11) sstore(1 - buf);
        __syncthreads();
    }

    float* out = g_Gp + (size_t)bz * BN * BN;
    const int r0 = rowA + wm*16 + gid;
    #pragma unroll
    for (int f = 0; f < 4; f++) {
        int col = rowB + wn*32 + f*8 + tig*2;
        *reinterpret_cast<float2*>(&out[(size_t)r0*BN + col]) =
            make_float2(acc[f][0], acc[f][1]);
        *reinterpret_cast<float2*>(&out[(size_t)(r0 + 8)*BN + col]) =
            make_float2(acc[f][2], acc[f][3]);
    }
}

__device__ void simK_part(uint32_t* smem, int blk,
                          const float* __restrict__ li,
                          const float* __restrict__ lt) {
    uint32_t* As32 = smem;                    // 2560 words (2 bufs 64*20)
    uint32_t* Bs32 = smem + 2560;             // 3200 words (2 bufs 80*20)
    float* normA = reinterpret_cast<float*>(smem + 5760);
    float* normB = normA + 64;

    const int b = blk / 3;
    const int c = blk - b*3;
    const float4* A4 = reinterpret_cast<const float4*>(li + ((size_t)(b*CC + c))*NP*DD);
    const float4* B4 = reinterpret_cast<const float4*>(lt + ((size_t)(b*CC + c))*NT*DD);

    const int t = threadIdx.x;
    const int lane = t & 31;
    const int w = t >> 5;

    const bool isA = (t < 98);
    const bool isB = (t >= 104);
    const int arow = t >> 1;
    const int tb = t - 104;
    const int brow = tb >> 1;
    const int q0A = (t & 1) * 4;
    const int q0B = (tb & 1) * 4;

    if (t < 64) normA[t] = 0.f;
    if (t >= 64 && t < 144) normB[t - 64] = 0.f;
    for (int e = t; e < (15 + 4) * 16 * 2; e += 256) {
        int bf = e & 1, e2 = e >> 1;
        int rr = e2 >> 4, ww = e2 & 15;
        if (rr < 15) As32[bf*1280 + (49 + rr)*20 + ww] = 0u;
        else         Bs32[bf*1600 + (76 + (rr - 15))*20 + ww] = 0u;
    }

    const int wm = w >> 1;
    const int wn = w & 1;
    const int gid = lane >> 2;
    const int tig = lane & 3;
    const int r0 = wm*16 + gid;
    const int r1 = r0 + 8;

    // ldmatrix per-lane base addresses (shared space, bytes)
    const uint32_t a_sh = (uint32_t)__cvta_generic_to_shared(As32);
    const uint32_t b_sh = (uint32_t)__cvta_generic_to_shared(Bs32);
    const int mi = lane >> 3;              // matrix index 0..3
    const int ri = lane & 7;               // row within matrix
    // A x4: mat0 rows 0-7 k0-7, mat1 rows 8-15 k0-7, mat2 rows 0-7 k8-15, mat3 rows 8-15 k8-15
    const uint32_t a_addr0 = a_sh +
        (((wm*16 + (mi & 1)*8 + ri) * 20) + ((mi >> 1) * 4)) * 4u;
    // B x2: mat0 rows n0-7 k0-7, mat1 rows n0-7 k8-15 (lanes 16-31 addrs unused but valid)
    const uint32_t b_addr0 = b_sh +
        (((wn*40 + ri) * 20) + (((lane >> 3) & 1) * 4)) * 4u;

    float acc[5][4];
    #pragma unroll
    for (int f = 0; f < 5; f++) {
        acc[f][0] = 0.f; acc[f][1] = 0.f; acc[f][2] = 0.f; acc[f][3] = 0.f;
    }

    float4 rv[4];
    auto issue_load = [&](int kc) {
        if (isA) {
            const float4* src = A4 + arow*192 + kc*8 + q0A;
            #pragma unroll
            for (int i = 0; i < 4; i++) rv[i] = src[i];
        } else if (isB) {
            const float4* src = B4 + brow*192 + kc*8 + q0B;
            #pragma unroll
            for (int i = 0; i < 4; i++) rv[i] = src[i];
        }
    };
    auto store_tile = [&](int bf) {
        float ss = 0.f;
        if (isA) {
            #pragma unroll
            for (int i = 0; i < 4; i++) {
                float4 v = rv[i];
                ss += v.x*v.x + v.y*v.y + v.z*v.z + v.w*v.w;
                int wbase = bf*1280 + arow*20 + (q0A + i)*2;
                As32[wbase]     = pack_bf16(v.x, v.y);
                As32[wbase + 1] = pack_bf16(v.z, v.w);
            }
        } else if (isB) {
            #pragma unroll
            for (int i = 0; i < 4; i++) {
                float4 v = rv[i];
                ss += v.x*v.x + v.y*v.y + v.z*v.z + v.w*v.w;
                int wbase = bf*1600 + brow*20 + (q0B + i)*2;
                Bs32[wbase]     = pack_bf16(v.x, v.y);
                Bs32[wbase + 1] = pack_bf16(v.z, v.w);
            }
        }
        ss += __shfl_xor_sync(0xffffffffu, ss, 1);
        if (isA && (t & 1) == 0) normA[arow] += ss;
        if (isB && (tb & 1) == 0) normB[brow] += ss;
    };

    issue_load(0);
    store_tile(0);
    __syncthreads();

    for (int kc = 0; kc < 24; kc++) {
        const int bf = kc & 1;
        if (kc < 23) issue_load(kc + 1);
        #pragma unroll
        for (int ks = 0; ks < 2; ks++) {
            const int kw = ks * 8;
            uint32_t a0, a1, a2, a3;
            ldsm_x4(a0, a1, a2, a3, a_addr0 + (bf*1280 + kw)*4u);
            #pragma unroll
            for (int f = 0; f < 5; f++) {
                uint32_t b0, b1;
                ldsm_x2(b0, b1, b_addr0 + (bf*1600 + kw)*4u + f*640u);
                asm volatile(
                    "mma.sync.aligned.m16n8k16.row.col.f32.bf16.bf16.f32 "
                    "{%0,%1,%2,%3}, {%4,%5,%6,%7}, {%8,%9}, {%0,%1,%2,%3};"
                    : "+f"(acc[f][0]), "+f"(acc[f][1]), "+f"(acc[f][2]), "+f"(acc[f][3])
                    : "r"(a0), "r"(a1), "r"(a2), "r"(a3), "r"(b0), "r"(b1));
            }
        }
        if (kc < 23) store_tile(1 - bf);
        __syncthreads();
    }

    if (t < 64)                normA[t]      = 1.0f / fmaxf(sqrtf(normA[t]), 1e-12f);
    if (t >= 64 && t < 144)    normB[t - 64] = 1.0f / fmaxf(sqrtf(normB[t - 64]), 1e-12f);
    __syncthreads();

    const size_t base = (size_t)(c*BN + b) * (NP*NT);
    const float ia0 = (r0 < NP) ? normA[r0] : 0.f;
    const float ia1 = (r1 < NP) ? normA[r1] : 0.f;
    #pragma unroll
    for (int f = 0; f < 5; f++) {
        int col = wn*40 + f*8 + tig*2;
        float ib0 = normB[col];
        float ib1 = normB[col + 1];
        if (col < NT) {
            if (r0 < NP) {
                float s0 = acc[f][0] * ia0 * ib0;
                float s1 = acc[f][1] * ia0 * ib1;
                g_K[base + (size_t)r0*NT + col] = expf(fmaf(10.0f, s0, -10.0f));
                if (col + 1 < NT)
                    g_K[base + (size_t)r0*NT + col + 1] = expf(fmaf(10.0f, s1, -10.0f));
            }
            if (r1 < NP) {
                float s2 = acc[f][2] * ia1 * ib0;
                float s3 = acc[f][3] * ia1 * ib1;
                g_K[base + (size_t)r1*NT + col] = expf(fmaf(10.0f, s2, -10.0f));
                if (col + 1 < NT)
                    g_K[base + (size_t)r1*NT + col + 1] = expf(fmaf(10.0f, s3, -10.0f));
            }
        }
    }
}

extern __shared__ uint32_t dynsmem[];
__global__ void __launch_bounds__(256, 5) fused_simK_gemm_kernel(
        const float* __restrict__ li, const float* __restrict__ lt,
        const float* __restrict__ img, const float* __restrict__ txt) {
    if (blockIdx.x == 0 && threadIdx.x == 0) {
        g_count = 0u; g_gen = 0u; g_fin1 = 0u; g_fin2 = 0u;   // per-replay reset
    }
    if (blockIdx.x < GEMM_BLKS) gemm_part(dynsmem, blockIdx.x, img, txt);
    else                        simK_part(dynsmem, blockIdx.x - GEMM_BLKS, li, lt);
}

// ------------------------- persistent Sinkhorn kernel ------------------------
// R10 barrier scheme + 4-way ILP dot products (from R12, proven).
extern __shared__ float sh[];
__global__ void __launch_bounds__(STPB) sinkhorn_kernel() {
    float* sK  = sh;                       // 12*SKP
    float* r_s = sK + 12*SKP;              // 12*52
    float* c_s = r_s + 12*52;              // 12*80
    __shared__ float errw[12];
    __shared__ float warp_part[16];
    __shared__ unsigned s_mask;

    const int tid = threadIdx.x;
    const int blk = blockIdx.x;
    const int lane = tid & 31;
    const int w = tid >> 5;

    for (int p = 0; p < 12; p++) {
        int ch = p >> 2;
        int b  = blk*4 + (p & 3);
        const float* src = g_K + (size_t)(ch*BN + b) * (NP*NT);
        for (int e = tid; e < NP*NT; e += STPB) {
            int n = e / NT, m = e - n*NT;
            sK[p*SKP + n*77 + m] = src[e];
        }
    }
    for (int e = tid; e < 12*52; e += STPB) r_s[e] = 1.0f;
    for (int e = tid; e < 12*80; e += STPB) c_s[e] = 1.0f;
    __syncthreads();

    unsigned gen = 0;
    unsigned mask = 7u;
    int it0 = 0, it1 = 0, it2 = 0;
    const float U = 1.0f / (float)NP;
    const float V = 1.0f / (float)NT;

    while (mask) {
        if (w < 12) {
            const int p = w, ch = p >> 2;
            float epart = 0.f;
            if (mask & (1u << ch)) {
                const float* Kp = &sK[p*SKP];
                float* rp = &r_s[p*52];
                float* cp = &c_s[p*80];
                #pragma unroll
                for (int rr = 0; rr < 2; rr++) {
                    int n = lane + rr*32;
                    if (n < NP) {
                        const float* Kr = Kp + n*77;
                        float s0 = 0.f, s1 = 0.f, s2 = 0.f, s3 = 0.f;
                        #pragma unroll
                        for (int m = 0; m < 76; m += 4) {
                            s0 = fmaf(Kr[m],   cp[m],   s0);
                            s1 = fmaf(Kr[m+1], cp[m+1], s1);
                            s2 = fmaf(Kr[m+2], cp[m+2], s2);
                            s3 = fmaf(Kr[m+3], cp[m+3], s3);
                        }
                        float s = (s0 + s1) + (s2 + s3);
                        float rn = U / s;
                        epart += fabsf(rn - rp[n]);
                        rp[n] = rn;
                    }
                }
                __syncwarp();
                #pragma unroll
                for (int cc = 0; cc < 3; cc++) {
                    int m = lane + cc*32;
                    if (m < NT) {
                        const float* Kc = Kp + m;
                        float s0 = 0.f, s1 = 0.f, s2 = 0.f, s3 = 0.f;
                        #pragma unroll
                        for (int n = 0; n < 48; n += 4) {
                            s0 = fmaf(Kc[(n  )*77], rp[n  ], s0);
                            s1 = fmaf(Kc[(n+1)*77], rp[n+1], s1);
                            s2 = fmaf(Kc[(n+2)*77], rp[n+2], s2);
                            s3 = fmaf(Kc[(n+3)*77], rp[n+3], s3);
                        }
                        float s = ((s0 + s1) + (s2 + s3)) + Kc[48*77]*rp[48];
                        cp[m] = V / s;
                    }
                }
                #pragma unroll
                for (int o = 16; o; o >>= 1)
                    epart += __shfl_xor_sync(0xffffffffu, epart, o);
            }
            if (lane == 0) errw[p] = epart;
        }
        __syncthreads();

        if (w == 0) {
            float e = (lane < 12) ? errw[lane] : 0.f;
            e += __shfl_xor_sync(0xffffffffu, e, 1);
            e += __shfl_xor_sync(0xffffffffu, e, 2);
            float s0 = __shfl_sync(0xffffffffu, e, 0);
            float s1 = __shfl_sync(0xffffffffu, e, 4);
            float s2 = __shfl_sync(0xffffffffu, e, 8);
            unsigned my = 0u;
            if (lane == 0) {
                g_err4[blk] = make_float4(s0, s1, s2, 0.f);
                __threadfence();
                my = atomicAdd(&g_count, 1u);
            }
            my = __shfl_sync(0xffffffffu, my, 0);
            gen++;
            if (my == NBLK - 1) {
                __threadfence();
                float a0 = 0.f, a1 = 0.f, a2 = 0.f;
                #pragma unroll
                for (int i2 = 0; i2 < 4; i2++) {
                    float4 e4 = __ldcg(&g_err4[lane*4 + i2]);
                    a0 += e4.x; a1 += e4.y; a2 += e4.z;
                }
                #pragma unroll
                for (int o = 16; o; o >>= 1) {
                    a0 += __shfl_xor_sync(0xffffffffu, a0, o);
                    a1 += __shfl_xor_sync(0xffffffffu, a1, o);
                    a2 += __shfl_xor_sync(0xffffffffu, a2, o);
                }
                if (lane == 0) {
                    unsigned nm = mask;
                    const float inv = 1.0f / (float)(BN*NP);
                    if (mask & 1u) { int it = it0 + 1;
                        if (!(it < MAX_ITER && a0*inv >= THRESH)) nm &= ~1u; }
                    if (mask & 2u) { int it = it1 + 1;
                        if (!(it < MAX_ITER && a1*inv >= THRESH)) nm &= ~2u; }
                    if (mask & 4u) { int it = it2 + 1;
                        if (!(it < MAX_ITER && a2*inv >= THRESH)) nm &= ~4u; }
                    atomicExch(&g_mask, nm);
                    g_count = 0u;
                    __threadfence();
                    atomicAdd(&g_gen, 1u);
                    s_mask = nm;
                }
            } else {
                if (lane == 0) {
                    unsigned cur;
                    while ((cur = ld_acq(&g_gen)) < gen) __nanosleep(64);
                    s_mask = ld_acq(&g_mask);
                }
            }
        }
        __syncthreads();
        if (mask & 1u) it0++;
        if (mask & 2u) it1++;
        if (mask & 4u) it2++;
        mask = s_mask;
    }

    // OT contribution: sum r*c*K*sim, sim = 1 + eps*log(K)
    float ot = 0.f;
    for (int p = 0; p < 12; p++) {
        const float* Kp = &sK[p*SKP];
        const float* rp = &r_s[p*52];
        const float* cp = &c_s[p*80];
        for (int e = tid; e < NP*NT; e += STPB) {
            int n = e / NT, m = e - n*NT;
            float Kv = Kp[n*77 + m];
            float simv = fmaf(EPSI, __logf(Kv), 1.0f);
            ot = fmaf(rp[n]*cp[m], Kv*simv, ot);
        }
    }
    #pragma unroll
    for (int o = 16; o; o >>= 1) ot += __shfl_xor_sync(0xffffffffu, ot, o);
    if (lane == 0) warp_part[w] = ot;
    __syncthreads();
    if (w == 0) {
        float v = (lane < 16) ? warp_part[lane] : 0.f;
        #pragma unroll
        for (int o = 8; o; o >>= 1) v += __shfl_xor_sync(0xffffffffu, v, o);
        if (lane == 0) g_ot_part[blk] = v;
    }
}

// ---------------- unified tail: row LSE -> grid barrier -> col LSE -> out ----
__device__ __forceinline__ float block_lse(float x0, float x1, float* sred,
                                           int t, int lane, int w) {
    float mx = fmaxf(x0, x1);
    #pragma unroll
    for (int o = 16; o; o >>= 1) mx = fmaxf(mx, __shfl_xor_sync(0xffffffffu, mx, o));
    if (lane == 0) sred[w] = mx;
    __syncthreads();
    if (w == 0) {
        float v = (lane < 8) ? sred[lane] : -3.4e38f;
        #pragma unroll
        for (int o = 4; o; o >>= 1) v = fmaxf(v, __shfl_xor_sync(0xffffffffu, v, o));
        if (lane == 0) sred[8] = v;
    }
    __syncthreads();
    float M = sred[8];
    float e = expf(x0 - M) + expf(x1 - M);
    #pragma unroll
    for (int o = 16; o; o >>= 1) e += __shfl_xor_sync(0xffffffffu, e, o);
    __syncthreads();
    if (lane == 0) sred[w] = e;
    __syncthreads();
    float lse = 0.f;
    if (w == 0) {
        float v = (lane < 8) ? sred[lane] : 0.f;
        #pragma unroll
        for (int o = 4; o; o >>= 1) v += __shfl_xor_sync(0xffffffffu, v, o);
        lse = M + logf(v);
    }
    return lse;                      // valid on warp 0 lane 0 only
}

__global__ void __launch_bounds__(256) tail_kernel(const float* __restrict__ scale_p,
                                                   float* __restrict__ out) {
    __shared__ float sred[9];
    const int b = blockIdx.x, t = threadIdx.x;
    const int lane = t & 31, w = t >> 5;
    const float s = scale_p[0] * (1.0f / (float)CC);

    float x0 = 0.f, x1 = 0.f;
    #pragma unroll
    for (int j = 0; j < KSPLIT; j++) {
        const float* row = g_Gp + (size_t)j*BN*BN + (size_t)b*BN;
        x0 += row[t];
        x1 += row[t + 256];
    }
    x0 *= s; x1 *= s;
    g_LT[(size_t)t*BN + b] = x0;
    g_LT[(size_t)(t + 256)*BN + b] = x1;

    float lse = block_lse(x0, x1, sred, t, lane, w);
    if (t == 0) {
        g_lse_row[b] = lse;
        __threadfence();
        atomicAdd(&g_fin1, 1u);
        while (ld_acq(&g_fin1) < (unsigned)BN) __nanosleep(64);
    }
    __syncthreads();
    __threadfence();

    float y0 = g_LT[(size_t)b*BN + t];
    float y1 = g_LT[(size_t)b*BN + t + 256];
    __syncthreads();
    float clse = block_lse(y0, y1, sred, t, lane, w);
    __shared__ unsigned isLast;
    if (t == 0) {
        g_lse_col[b] = clse;
        __threadfence();
        isLast = (atomicAdd(&g_fin2, 1u) == (unsigned)(BN - 1));
    }
    __syncthreads();

    if (isLast) {
        __threadfence();
        float a1 = 0.f, a2 = 0.f, a3 = 0.f;
        #pragma unroll
        for (int h = 0; h < 2; h++) {
            int i = t + h*256;
            float diag = __ldcg(&g_LT[(size_t)i * BN + i]);
            a1 += __ldcg(&g_lse_row[i]) - diag;
            a2 += __ldcg(&g_lse_col[i]) - diag;
            if (i < NBLK) a3 += __ldcg(&g_ot_part[i]);
        }
        float v = a1 + a2;
        #pragma unroll
        for (int o = 16; o; o >>= 1) {
            v  += __shfl_xor_sync(0xffffffffu, v, o);
            a3 += __shfl_xor_sync(0xffffffffu, a3, o);
        }
        __syncthreads();
        __shared__ float sv[9], s3[9];
        if (lane == 0) { sv[w] = v; s3[w] = a3; }
        __syncthreads();
        if (w == 0) {
            float vv = (lane < 8) ? sv[lane] : 0.f;
            float v3 = (lane < 8) ? s3[lane] : 0.f;
            #pragma unroll
            for (int o = 4; o; o >>= 1) {
                vv += __shfl_xor_sync(0xffffffffu, vv, o);
                v3 += __shfl_xor_sync(0xffffffffu, v3, o);
            }
            if (lane == 0)
                out[0] = vv * (0.5f / (float)BN) + v3;
        }
    }
}

// ------------------------------- launch --------------------------------------
extern "C" void kernel_launch(void* const* d_in, const int* in_sizes, int n_in,
                              void* d_out, int out_size) {
    (void)in_sizes; (void)n_in; (void)out_size;
    const float* img   = (const float*)d_in[0];
    const float* txt   = (const float*)d_in[1];
    const float* scale = (const float*)d_in[2];
    const float* li    = (const float*)d_in[3];
    const float* lt    = (const float*)d_in[4];
    float* out = (float*)d_out;

    const size_t fused_smem = 9216 * sizeof(uint32_t);   // 36864 B
    const size_t sk_smem = (size_t)(12*SKP + 12*52 + 12*80) * sizeof(float);
    cudaFuncSetAttribute(sinkhorn_kernel,
                         cudaFuncAttributeMaxDynamicSharedMemorySize, (int)sk_smem);

    fused_simK_gemm_kernel<<<GEMM_BLKS + BN*CC, 256, fused_smem>>>(li, lt, img, txt);
    sinkhorn_kernel<<<NBLK, STPB, sk_smem>>>();
    tail_kernel<<<BN, 256>>>(scale, out);
}

// round 15
// speedup vs baseline: 1.1275x; 1.1275x over previous
#include <cuda_runtime.h>
#include <cuda_bf16.h>
#include <cstdint>
#include <math.h>

#define BN 512
#define CC 3
#define NP 49
#define NT 76
#define DD 768
#define EPSI 0.1f
#define THRESH 0.01f
#define MAX_ITER 100

#define NBLK 128          // sinkhorn persistent blocks
#define STPB 512          // sinkhorn threads per block (16 warps)
#define SKP (49*77)       // padded K tile stride (3773 floats)
#define KSPLIT 6
#define GEMM_BLKS 384     // 8 x 8 x 6 split-K tiles

// ------------------------- device scratch (no allocs allowed) ----------------
__device__ float g_K[(size_t)CC*BN*NP*NT];        // exp kernel per (c,b)
__device__ float g_Gp[(size_t)KSPLIT*BN*BN];      // split-K partials of logits GEMM
__device__ float g_LT[(size_t)BN*BN];             // logits TRANSPOSED [col][row]
__device__ float g_lse_row[BN];
__device__ float g_lse_col[BN];
__device__ float4 g_err4[NBLK];
__device__ float g_ot_part[NBLK];
__device__ unsigned g_count;
__device__ unsigned g_gen;
__device__ unsigned g_mask;
__device__ unsigned g_fin1;
__device__ unsigned g_fin2;

__device__ __forceinline__ uint32_t pack_bf16(float x, float y) {
    __nv_bfloat162 h = __floats2bfloat162_rn(x, y);  // .x = low 16 bits
    return *reinterpret_cast<uint32_t*>(&h);
}
__device__ __forceinline__ uint32_t f2tf(float x) {
    uint32_t r;
    asm("cvt.rna.tf32.f32 %0, %1;" : "=r"(r) : "f"(x));
    return r;
}
__device__ __forceinline__ unsigned ld_acq(const unsigned* p) {
    unsigned v;
    asm volatile("ld.acquire.gpu.u32 %0, [%1];" : "=r"(v) : "l"(p));
    return v;
}
__device__ __forceinline__ void ldsm_x4(uint32_t& d0, uint32_t& d1,
                                        uint32_t& d2, uint32_t& d3, uint32_t addr) {
    asm volatile("ldmatrix.sync.aligned.m8n8.x4.shared.b16 {%0,%1,%2,%3}, [%4];"
                 : "=r"(d0), "=r"(d1), "=r"(d2), "=r"(d3) : "r"(addr));
}
__device__ __forceinline__ void ldsm_x2(uint32_t& d0, uint32_t& d1, uint32_t addr) {
    asm volatile("ldmatrix.sync.aligned.m8n8.x2.shared.b16 {%0,%1}, [%2];"
                 : "=r"(d0), "=r"(d1) : "r"(addr));
}

// ---------------- fused kernel: logits GEMM (blocks 0..383) ------------------
//                + simK        (blocks 384..1919)
__device__ void gemm_part(uint32_t* smem, int g,
                          const float* __restrict__ img,
                          const float* __restrict__ txt) {
    uint32_t* As = smem;            // 4608 words (2 bufs of 64*36)
    uint32_t* Bs = smem + 4608;     // 4608 words
    const int bz = g >> 6;
    const int by = (g & 63) >> 3;
    const int bx = g & 7;
    const int t = threadIdx.x;
    const int lane = t & 31, w = t >> 5;
    const int gid = lane >> 2, tig = lane & 3;
    const int wm = w >> 1, wn = w & 1;
    const int rowA = by * 64, rowB = bx * 64;
    const float4* A4 = reinterpret_cast<const float4*>(img);
    const float4* B4 = reinterpret_cast<const float4*>(txt);
    const int lr = t >> 2;
    const int lj = t & 3;
    const int kbase = bz * 96;

    float acc[4][4];
    #pragma unroll
    for (int f = 0; f < 4; f++) {
        acc[f][0] = 0.f; acc[f][1] = 0.f; acc[f][2] = 0.f; acc[f][3] = 0.f;
    }

    float4 va0, va1, vb0, vb1;
    auto gload = [&](int kc) {
        const size_t offA = (size_t)(rowA + lr)*576 + kbase + kc*8 + lj*2;
        const size_t offB = (size_t)(rowB + lr)*576 + kbase + kc*8 + lj*2;
        va0 = A4[offA]; va1 = A4[offA + 1];
        vb0 = B4[offB]; vb1 = B4[offB + 1];
    };
    auto sstore = [&](int buf) {
        uint4* pa = reinterpret_cast<uint4*>(&As[buf*2304 + lr*36 + lj*8]);
        uint4* pb = reinterpret_cast<uint4*>(&Bs[buf*2304 + lr*36 + lj*8]);
        pa[0] = make_uint4(f2tf(va0.x), f2tf(va0.y), f2tf(va0.z), f2tf(va0.w));
        pa[1] = make_uint4(f2tf(va1.x), f2tf(va1.y), f2tf(va1.z), f2tf(va1.w));
        pb[0] = make_uint4(f2tf(vb0.x), f2tf(vb0.y), f2tf(vb0.z), f2tf(vb0.w));
        pb[1] = make_uint4(f2tf(vb1.x), f2tf(vb1.y), f2tf(vb1.z), f2tf(vb1.w));
    };

    gload(0);
    sstore(0);
    __syncthreads();

    for (int kc = 0; kc < 12; kc++) {
        const int buf = kc & 1;
        const uint32_t* Ab = &As[buf*2304];
        const uint32_t* Bb = &Bs[buf*2304];
        if (kc < 11) gload(kc + 1);
        #pragma unroll
        for (int ks = 0; ks < 4; ks++) {
            const int kw = ks * 8;
            uint32_t a0 = Ab[(wm*16 + gid)*36 + kw + tig];
            uint32_t a1 = Ab[(wm*16 + gid + 8)*36 + kw + tig];
            uint32_t a2 = Ab[(wm*16 + gid)*36 + kw + 4 + tig];
            uint32_t a3 = Ab[(wm*16 + gid + 8)*36 + kw + 4 + tig];
            #pragma unroll
            for (int f = 0; f < 4; f++) {
                int col = wn*32 + f*8 + gid;
                uint32_t b0 = Bb[col*36 + kw + tig];
                uint32_t b1 = Bb[col*36 + kw + 4 + tig];
                asm volatile(
                    "mma.sync.aligned.m16n8k8.row.col.f32.tf32.tf32.f32 "
                    "{%0,%1,%2,%3}, {%4,%5,%6,%7}, {%8,%9}, {%0,%1,%2,%3};"
                    : "+f"(acc[f][0]), "+f"(acc[f][1]), "+f"(acc[f][2]), "+f"(acc[f][3])
                    : "r"(a0), "r"(a1), "r"(a2), "r"(a3), "r"(b0), "r"(b1));
            }
        }
        if (kc < 11) sstore(1 - buf);
        __syncthreads();
    }

    float* out = g_Gp + (size_t)bz * BN * BN;
    const int r0 = rowA + wm*16 + gid;
    #pragma unroll
    for (int f = 0; f < 4; f++) {
        int col = rowB + wn*32 + f*8 + tig*2;
        *reinterpret_cast<float2*>(&out[(size_t)r0*BN + col]) =
            make_float2(acc[f][0], acc[f][1]);
        *reinterpret_cast<float2*>(&out[(size_t)(r0 + 8)*BN + col]) =
            make_float2(acc[f][2], acc[f][3]);
    }
}

__device__ void simK_part(uint32_t* smem, int blk,
                          const float* __restrict__ li,
                          const float* __restrict__ lt) {
    uint32_t* As32 = smem;                    // 2560 words (2 bufs 64*20)
    uint32_t* Bs32 = smem + 2560;             // 3200 words (2 bufs 80*20)
    float* normA = reinterpret_cast<float*>(smem + 5760);
    float* normB = normA + 64;

    const int b = blk / 3;
    const int c = blk - b*3;
    const float4* A4 = reinterpret_cast<const float4*>(li + ((size_t)(b*CC + c))*NP*DD);
    const float4* B4 = reinterpret_cast<const float4*>(lt + ((size_t)(b*CC + c))*NT*DD);

    const int t = threadIdx.x;
    const int lane = t & 31;
    const int w = t >> 5;

    const bool isA = (t < 98);
    const bool isB = (t >= 104);
    const int arow = t >> 1;
    const int tb = t - 104;
    const int brow = tb >> 1;
    const int q0A = (t & 1) * 4;
    const int q0B = (tb & 1) * 4;

    if (t < 64) normA[t] = 0.f;
    if (t >= 64 && t < 144) normB[t - 64] = 0.f;
    for (int e = t; e < (15 + 4) * 16 * 2; e += 256) {
        int bf = e & 1, e2 = e >> 1;
        int rr = e2 >> 4, ww = e2 & 15;
        if (rr < 15) As32[bf*1280 + (49 + rr)*20 + ww] = 0u;
        else         Bs32[bf*1600 + (76 + (rr - 15))*20 + ww] = 0u;
    }

    const int wm = w >> 1;
    const int wn = w & 1;
    const int gid = lane >> 2;
    const int tig = lane & 3;
    const int r0 = wm*16 + gid;
    const int r1 = r0 + 8;

    // ldmatrix per-lane base addresses (shared space, bytes)
    const uint32_t a_sh = (uint32_t)__cvta_generic_to_shared(As32);
    const uint32_t b_sh = (uint32_t)__cvta_generic_to_shared(Bs32);
    const int mi = lane >> 3;              // matrix index 0..3
    const int ri = lane & 7;               // row within matrix
    // A x4: mat0 rows 0-7 k0-7, mat1 rows 8-15 k0-7, mat2 rows 0-7 k8-15, mat3 rows 8-15 k8-15
    const uint32_t a_addr0 = a_sh +
        (((wm*16 + (mi & 1)*8 + ri) * 20) + ((mi >> 1) * 4)) * 4u;
    // B x2: mat0 rows n0-7 k0-7, mat1 rows n0-7 k8-15 (lanes 16-31 addrs unused but valid)
    const uint32_t b_addr0 = b_sh +
        (((wn*40 + ri) * 20) + (((lane >> 3) & 1) * 4)) * 4u;

    float acc[5][4];
    #pragma unroll
    for (int f = 0; f < 5; f++) {
        acc[f][0] = 0.f; acc[f][1] = 0.f; acc[f][2] = 0.f; acc[f][3] = 0.f;
    }

    float4 rv[4];
    auto issue_load = [&](int kc) {
        if (isA) {
            const float4* src = A4 + arow*192 + kc*8 + q0A;
            #pragma unroll
            for (int i = 0; i < 4; i++) rv[i] = src[i];
        } else if (isB) {
            const float4* src = B4 + brow*192 + kc*8 + q0B;
            #pragma unroll
            for (int i = 0; i < 4; i++) rv[i] = src[i];
        }
    };
    auto store_tile = [&](int bf) {
        float ss = 0.f;
        if (isA) {
            #pragma unroll
            for (int i = 0; i < 4; i++) {
                float4 v = rv[i];
                ss += v.x*v.x + v.y*v.y + v.z*v.z + v.w*v.w;
                int wbase = bf*1280 + arow*20 + (q0A + i)*2;
                As32[wbase]     = pack_bf16(v.x, v.y);
                As32[wbase + 1] = pack_bf16(v.z, v.w);
            }
        } else if (isB) {
            #pragma unroll
            for (int i = 0; i < 4; i++) {
                float4 v = rv[i];
                ss += v.x*v.x + v.y*v.y + v.z*v.z + v.w*v.w;
                int wbase = bf*1600 + brow*20 + (q0B + i)*2;
                Bs32[wbase]     = pack_bf16(v.x, v.y);
                Bs32[wbase + 1] = pack_bf16(v.z, v.w);
            }
        }
        ss += __shfl_xor_sync(0xffffffffu, ss, 1);
        if (isA && (t & 1) == 0) normA[arow] += ss;
        if (isB && (tb & 1) == 0) normB[brow] += ss;
    };

    issue_load(0);
    store_tile(0);
    __syncthreads();

    for (int kc = 0; kc < 24; kc++) {
        const int bf = kc & 1;
        if (kc < 23) issue_load(kc + 1);
        #pragma unroll
        for (int ks = 0; ks < 2; ks++) {
            const int kw = ks * 8;
            uint32_t a0, a1, a2, a3;
            ldsm_x4(a0, a1, a2, a3, a_addr0 + (bf*1280 + kw)*4u);
            #pragma unroll
            for (int f = 0; f < 5; f++) {
                uint32_t b0, b1;
                ldsm_x2(b0, b1, b_addr0 + (bf*1600 + kw)*4u + f*640u);
                asm volatile(
                    "mma.sync.aligned.m16n8k16.row.col.f32.bf16.bf16.f32 "
                    "{%0,%1,%2,%3}, {%4,%5,%6,%7}, {%8,%9}, {%0,%1,%2,%3};"
                    : "+f"(acc[f][0]), "+f"(acc[f][1]), "+f"(acc[f][2]), "+f"(acc[f][3])
                    : "r"(a0), "r"(a1), "r"(a2), "r"(a3), "r"(b0), "r"(b1));
            }
        }
        if (kc < 23) store_tile(1 - bf);
        __syncthreads();
    }

    if (t < 64)                normA[t]      = 1.0f / fmaxf(sqrtf(normA[t]), 1e-12f);
    if (t >= 64 && t < 144)    normB[t - 64] = 1.0f / fmaxf(sqrtf(normB[t - 64]), 1e-12f);
    __syncthreads();

    const size_t base = (size_t)(c*BN + b) * (NP*NT);
    const float ia0 = (r0 < NP) ? normA[r0] : 0.f;
    const float ia1 = (r1 < NP) ? normA[r1] : 0.f;
    #pragma unroll
    for (int f = 0; f < 5; f++) {
        int col = wn*40 + f*8 + tig*2;
        float ib0 = normB[col];
        float ib1 = normB[col + 1];
        if (col < NT) {
            if (r0 < NP) {
                float s0 = acc[f][0] * ia0 * ib0;
                float s1 = acc[f][1] * ia0 * ib1;
                g_K[base + (size_t)r0*NT + col] = expf(fmaf(10.0f, s0, -10.0f));
                if (col + 1 < NT)
                    g_K[base + (size_t)r0*NT + col + 1] = expf(fmaf(10.0f, s1, -10.0f));
            }
            if (r1 < NP) {
                float s2 = acc[f][2] * ia1 * ib0;
                float s3 = acc[f][3] * ia1 * ib1;
                g_K[base + (size_t)r1*NT + col] = expf(fmaf(10.0f, s2, -10.0f));
                if (col + 1 < NT)
                    g_K[base + (size_t)r1*NT + col + 1] = expf(fmaf(10.0f, s3, -10.0f));
            }
        }
    }
}

extern __shared__ uint32_t dynsmem[];
__global__ void __launch_bounds__(256) fused_simK_gemm_kernel(
        const float* __restrict__ li, const float* __restrict__ lt,
        const float* __restrict__ img, const float* __restrict__ txt) {
    if (blockIdx.x == 0 && threadIdx.x == 0) {
        g_count = 0u; g_gen = 0u; g_fin1 = 0u; g_fin2 = 0u;   // per-replay reset
    }
    if (blockIdx.x < GEMM_BLKS) gemm_part(dynsmem, blockIdx.x, img, txt);
    else                        simK_part(dynsmem, blockIdx.x - GEMM_BLKS, li, lt);
}

// ------------------------- persistent Sinkhorn kernel ------------------------
// R10 barrier scheme + 4-way ILP dot products (from R12, proven).
extern __shared__ float sh[];
__global__ void __launch_bounds__(STPB) sinkhorn_kernel() {
    float* sK  = sh;                       // 12*SKP
    float* r_s = sK + 12*SKP;              // 12*52
    float* c_s = r_s + 12*52;              // 12*80
    __shared__ float errw[12];
    __shared__ float warp_part[16];
    __shared__ unsigned s_mask;

    const int tid = threadIdx.x;
    const int blk = blockIdx.x;
    const int lane = tid & 31;
    const int w = tid >> 5;

    for (int p = 0; p < 12; p++) {
        int ch = p >> 2;
        int b  = blk*4 + (p & 3);
        const float* src = g_K + (size_t)(ch*BN + b) * (NP*NT);
        for (int e = tid; e < NP*NT; e += STPB) {
            int n = e / NT, m = e - n*NT;
            sK[p*SKP + n*77 + m] = src[e];
        }
    }
    for (int e = tid; e < 12*52; e += STPB) r_s[e] = 1.0f;
    for (int e = tid; e < 12*80; e += STPB) c_s[e] = 1.0f;
    __syncthreads();

    unsigned gen = 0;
    unsigned mask = 7u;
    int it0 = 0, it1 = 0, it2 = 0;
    const float U = 1.0f / (float)NP;
    const float V = 1.0f / (float)NT;

    while (mask) {
        if (w < 12) {
            const int p = w, ch = p >> 2;
            float epart = 0.f;
            if (mask & (1u << ch)) {
                const float* Kp = &sK[p*SKP];
                float* rp = &r_s[p*52];
                float* cp = &c_s[p*80];
                #pragma unroll
                for (int rr = 0; rr < 2; rr++) {
                    int n = lane + rr*32;
                    if (n < NP) {
                        const float* Kr = Kp + n*77;
                        float s0 = 0.f, s1 = 0.f, s2 = 0.f, s3 = 0.f;
                        #pragma unroll
                        for (int m = 0; m < 76; m += 4) {
                            s0 = fmaf(Kr[m],   cp[m],   s0);
                            s1 = fmaf(Kr[m+1], cp[m+1], s1);
                            s2 = fmaf(Kr[m+2], cp[m+2], s2);
                            s3 = fmaf(Kr[m+3], cp[m+3], s3);
                        }
                        float s = (s0 + s1) + (s2 + s3);
                        float rn = U / s;
                        epart += fabsf(rn - rp[n]);
                        rp[n] = rn;
                    }
                }
                __syncwarp();
                #pragma unroll
                for (int cc = 0; cc < 3; cc++) {
                    int m = lane + cc*32;
                    if (m < NT) {
                        const float* Kc = Kp + m;
                        float s0 = 0.f, s1 = 0.f, s2 = 0.f, s3 = 0.f;
                        #pragma unroll
                        for (int n = 0; n < 48; n += 4) {
                            s0 = fmaf(Kc[(n  )*77], rp[n  ], s0);
                            s1 = fmaf(Kc[(n+1)*77], rp[n+1], s1);
                            s2 = fmaf(Kc[(n+2)*77], rp[n+2], s2);
                            s3 = fmaf(Kc[(n+3)*77], rp[n+3], s3);
                        }
                        float s = ((s0 + s1) + (s2 + s3)) + Kc[48*77]*rp[48];
                        cp[m] = V / s;
                    }
                }
                #pragma unroll
                for (int o = 16; o; o >>= 1)
                    epart += __shfl_xor_sync(0xffffffffu, epart, o);
            }
            if (lane == 0) errw[p] = epart;
        }
        __syncthreads();

        if (w == 0) {
            float e = (lane < 12) ? errw[lane] : 0.f;
            e += __shfl_xor_sync(0xffffffffu, e, 1);
            e += __shfl_xor_sync(0xffffffffu, e, 2);
            float s0 = __shfl_sync(0xffffffffu, e, 0);
            float s1 = __shfl_sync(0xffffffffu, e, 4);
            float s2 = __shfl_sync(0xffffffffu, e, 8);
            unsigned my = 0u;
            if (lane == 0) {
                g_err4[blk] = make_float4(s0, s1, s2, 0.f);
                __threadfence();
                my = atomicAdd(&g_count, 1u);
            }
            my = __shfl_sync(0xffffffffu, my, 0);
            gen++;
            if (my == NBLK - 1) {
                __threadfence();
                float a0 = 0.f, a1 = 0.f, a2 = 0.f;
                #pragma unroll
                for (int i2 = 0; i2 < 4; i2++) {
                    float4 e4 = __ldcg(&g_err4[lane*4 + i2]);
                    a0 += e4.x; a1 += e4.y; a2 += e4.z;
                }
                #pragma unroll
                for (int o = 16; o; o >>= 1) {
                    a0 += __shfl_xor_sync(0xffffffffu, a0, o);
                    a1 += __shfl_xor_sync(0xffffffffu, a1, o);
                    a2 += __shfl_xor_sync(0xffffffffu, a2, o);
                }
                if (lane == 0) {
                    unsigned nm = mask;
                    const float inv = 1.0f / (float)(BN*NP);
                    if (mask & 1u) { int it = it0 + 1;
                        if (!(it < MAX_ITER && a0*inv >= THRESH)) nm &= ~1u; }
                    if (mask & 2u) { int it = it1 + 1;
                        if (!(it < MAX_ITER && a1*inv >= THRESH)) nm &= ~2u; }
                    if (mask & 4u) { int it = it2 + 1;
                        if (!(it < MAX_ITER && a2*inv >= THRESH)) nm &= ~4u; }
                    atomicExch(&g_mask, nm);
                    g_count = 0u;
                    __threadfence();
                    atomicAdd(&g_gen, 1u);
                    s_mask = nm;
                }
            } else {
                if (lane == 0) {
                    unsigned cur;
                    while ((cur = ld_acq(&g_gen)) < gen) __nanosleep(64);
                    s_mask = ld_acq(&g_mask);
                }
            }
        }
        __syncthreads();
        if (mask & 1u) it0++;
        if (mask & 2u) it1++;
        if (mask & 4u) it2++;
        mask = s_mask;
    }

    // OT contribution: sum r*c*K*sim, sim = 1 + eps*log(K)
    float ot = 0.f;
    for (int p = 0; p < 12; p++) {
        const float* Kp = &sK[p*SKP];
        const float* rp = &r_s[p*52];
        const float* cp = &c_s[p*80];
        for (int e = tid; e < NP*NT; e += STPB) {
            int n = e / NT, m = e - n*NT;
            float Kv = Kp[n*77 + m];
            float simv = fmaf(EPSI, __logf(Kv), 1.0f);
            ot = fmaf(rp[n]*cp[m], Kv*simv, ot);
        }
    }
    #pragma unroll
    for (int o = 16; o; o >>= 1) ot += __shfl_xor_sync(0xffffffffu, ot, o);
    if (lane == 0) warp_part[w] = ot;
    __syncthreads();
    if (w == 0) {
        float v = (lane < 16) ? warp_part[lane] : 0.f;
        #pragma unroll
        for (int o = 8; o; o >>= 1) v += __shfl_xor_sync(0xffffffffu, v, o);
        if (lane == 0) g_ot_part[blk] = v;
    }
}

// ---------------- unified tail: row LSE -> grid barrier -> col LSE -> out ----
__device__ __forceinline__ float block_lse(float x0, float x1, float* sred,
                                           int t, int lane, int w) {
    float mx = fmaxf(x0, x1);
    #pragma unroll
    for (int o = 16; o; o >>= 1) mx = fmaxf(mx, __shfl_xor_sync(0xffffffffu, mx, o));
    if (lane == 0) sred[w] = mx;
    __syncthreads();
    if (w == 0) {
        float v = (lane < 8) ? sred[lane] : -3.4e38f;
        #pragma unroll
        for (int o = 4; o; o >>= 1) v = fmaxf(v, __shfl_xor_sync(0xffffffffu, v, o));
        if (lane == 0) sred[8] = v;
    }
    __syncthreads();
    float M = sred[8];
    float e = expf(x0 - M) + expf(x1 - M);
    #pragma unroll
    for (int o = 16; o; o >>= 1) e += __shfl_xor_sync(0xffffffffu, e, o);
    __syncthreads();
    if (lane == 0) sred[w] = e;
    __syncthreads();
    float lse = 0.f;
    if (w == 0) {
        float v = (lane < 8) ? sred[lane] : 0.f;
        #pragma unroll
        for (int o = 4; o; o >>= 1) v += __shfl_xor_sync(0xffffffffu, v, o);
        lse = M + logf(v);
    }
    return lse;                      // valid on warp 0 lane 0 only
}

__global__ void __launch_bounds__(256) tail_kernel(const float* __restrict__ scale_p,
                                                   float* __restrict__ out) {
    __shared__ float sred[9];
    const int b = blockIdx.x, t = threadIdx.x;
    const int lane = t & 31, w = t >> 5;
    const float s = scale_p[0] * (1.0f / (float)CC);

    float x0 = 0.f, x1 = 0.f;
    #pragma unroll
    for (int j = 0; j < KSPLIT; j++) {
        const float* row = g_Gp + (size_t)j*BN*BN + (size_t)b*BN;
        x0 += row[t];
        x1 += row[t + 256];
    }
    x0 *= s; x1 *= s;
    g_LT[(size_t)t*BN + b] = x0;
    g_LT[(size_t)(t + 256)*BN + b] = x1;

    float lse = block_lse(x0, x1, sred, t, lane, w);
    if (t == 0) {
        g_lse_row[b] = lse;
        __threadfence();
        atomicAdd(&g_fin1, 1u);
        while (ld_acq(&g_fin1) < (unsigned)BN) __nanosleep(64);
    }
    __syncthreads();
    __threadfence();

    float y0 = g_LT[(size_t)b*BN + t];
    float y1 = g_LT[(size_t)b*BN + t + 256];
    __syncthreads();
    float clse = block_lse(y0, y1, sred, t, lane, w);
    __shared__ unsigned isLast;
    if (t == 0) {
        g_lse_col[b] = clse;
        __threadfence();
        isLast = (atomicAdd(&g_fin2, 1u) == (unsigned)(BN - 1));
    }
    __syncthreads();

    if (isLast) {
        __threadfence();
        float a1 = 0.f, a2 = 0.f, a3 = 0.f;
        #pragma unroll
        for (int h = 0; h < 2; h++) {
            int i = t + h*256;
            float diag = __ldcg(&g_LT[(size_t)i * BN + i]);
            a1 += __ldcg(&g_lse_row[i]) - diag;
            a2 += __ldcg(&g_lse_col[i]) - diag;
            if (i < NBLK) a3 += __ldcg(&g_ot_part[i]);
        }
        float v = a1 + a2;
        #pragma unroll
        for (int o = 16; o; o >>= 1) {
            v  += __shfl_xor_sync(0xffffffffu, v, o);
            a3 += __shfl_xor_sync(0xffffffffu, a3, o);
        }
        __syncthreads();
        __shared__ float sv[9], s3[9];
        if (lane == 0) { sv[w] = v; s3[w] = a3; }
        __syncthreads();
        if (w == 0) {
            float vv = (lane < 8) ? sv[lane] : 0.f;
            float v3 = (lane < 8) ? s3[lane] : 0.f;
            #pragma unroll
            for (int o = 4; o; o >>= 1) {
                vv += __shfl_xor_sync(0xffffffffu, vv, o);
                v3 += __shfl_xor_sync(0xffffffffu, v3, o);
            }
            if (lane == 0)
                out[0] = vv * (0.5f / (float)BN) + v3;
        }
    }
}

// ------------------------------- launch --------------------------------------
extern "C" void kernel_launch(void* const* d_in, const int* in_sizes, int n_in,
                              void* d_out, int out_size) {
    (void)in_sizes; (void)n_in; (void)out_size;
    const float* img   = (const float*)d_in[0];
    const float* txt   = (const float*)d_in[1];
    const float* scale = (const float*)d_in[2];
    const float* li    = (const float*)d_in[3];
    const float* lt    = (const float*)d_in[4];
    float* out = (float*)d_out;

    const size_t fused_smem = 9216 * sizeof(uint32_t);   // 36864 B
    const size_t sk_smem = (size_t)(12*SKP + 12*52 + 12*80) * sizeof(float);
    cudaFuncSetAttribute(sinkhorn_kernel,
                         cudaFuncAttributeMaxDynamicSharedMemorySize, (int)sk_smem);

    fused_simK_gemm_kernel<<<GEMM_BLKS + BN*CC, 256, fused_smem>>>(li, lt, img, txt);
    sinkhorn_kernel<<<NBLK, STPB, sk_smem>>>();
    tail_kernel<<<BN, 256>>>(scale, out);
}